// round 1
// baseline (speedup 1.0000x reference)
#include <cuda_runtime.h>
#include <math.h>
#include <stdint.h>

// Problem constants
#define BB 32
#define CC 256
#define HH 32
#define WW 32
#define HP 34
#define WP 34

// Scratch (device globals -- no allocation allowed)
__device__ int8_t g_xq[(size_t)BB * HP * WP * CC];      // [b][h+1][w+1][c] int8, zero-padded halo
__device__ int8_t g_wq[(size_t)CC * 4 * 9 * 64];        // [o][cchunk(4)][tap(9)][cr(64)] int8 ternary
__device__ float  g_scale[CC];                          // gamma / sqrt(var+eps)
__device__ float  g_bias[CC];                           // beta - mean*inv

// ---------------------------------------------------------------------------
// Pre-pass A: quantize x to int8 (scale 2^-7) and transpose NCHW -> padded NHWC
// grid (32 b, 32 h), 256 threads
// ---------------------------------------------------------------------------
__global__ void quantX_kernel(const float* __restrict__ x) {
    __shared__ int8_t s[256][33];   // [c][w], padded
    int b = blockIdx.x, h = blockIdx.y;
    int w  = threadIdx.x & 31;
    int cg = threadIdx.x >> 5;
#pragma unroll
    for (int c0 = 0; c0 < 256; c0 += 8) {
        int c = c0 + cg;
        float v = x[(((size_t)(b * 256 + c) * 32 + h) * 32) + w];  // coalesced over w
        float r = rintf(v * 128.0f);                               // round-half-even == jnp.round
        r = fminf(fmaxf(r, -128.0f), 127.0f);
        s[c][w] = (int8_t)(int)r;
    }
    __syncthreads();
    size_t base = (((size_t)(b * 34 + h + 1)) * 34 + 1) * 256;     // padded row h+1, col offset 1
#pragma unroll
    for (int it = 0; it < 8; ++it) {
        int idx = it * 256 + threadIdx.x;
        int w2 = idx >> 6, cw = idx & 63;
        char4 v;
        v.x = s[cw * 4 + 0][w2];
        v.y = s[cw * 4 + 1][w2];
        v.z = s[cw * 4 + 2][w2];
        v.w = s[cw * 4 + 3][w2];
        *reinterpret_cast<char4*>(&g_xq[base + (size_t)w2 * 256 + cw * 4]) = v; // coalesced
    }
}

// ---------------------------------------------------------------------------
// Pre-pass B: quantize weights to ternary int8, repack OIHW -> [o][cc][t][cr]
// grid 2304 blocks x 256 threads (589824 elements)
// ---------------------------------------------------------------------------
__global__ void quantW_kernel(const float* __restrict__ wt) {
    int idx = blockIdx.x * 256 + threadIdx.x;
    int cr   = idx & 63;
    int tmp  = idx >> 6;
    int t    = tmp % 9;
    int tmp2 = tmp / 9;
    int cc   = tmp2 & 3;
    int o    = tmp2 >> 2;
    int c    = cc * 64 + cr;
    float v = wt[((size_t)(o * 256 + c)) * 9 + t];   // OIHW: [o][c][ky][kx], t=ky*3+kx
    float r = rintf(v);
    r = fminf(fmaxf(r, -1.0f), 1.0f);
    g_wq[idx] = (int8_t)(int)r;
}

// ---------------------------------------------------------------------------
// Pre-pass C: BN folding (inference).
// inv computed via double to get the correctly-rounded fp32 value.
// ---------------------------------------------------------------------------
__global__ void bn_kernel(const float* __restrict__ g, const float* __restrict__ be,
                          const float* __restrict__ m, const float* __restrict__ v) {
    int o = threadIdx.x;
    double invd = (double)g[o] / sqrt((double)v[o] + 1e-4);
    float invf = (float)invd;
    g_scale[o] = invf;
    g_bias[o]  = __fadd_rn(be[o], -__fmul_rn(m[o], invf));
}

// ---------------------------------------------------------------------------
// Conv: implicit GEMM with dp4a.
// grid (b=32, h/4=8, o/64=4), 256 threads.
// Each CTA: 64 o x 4 h x 32 w outputs; thread = (og 0..7, w 0..31), 8o x 4h accs.
// smem: X [6 rows][16 cw][34 wp] (transposed, conflict-free), W [64 o][9 t][16 cw].
// 4 chunks of 64 input channels.
// ---------------------------------------------------------------------------
__global__ void __launch_bounds__(256) conv_kernel(float* __restrict__ out) {
    extern __shared__ int smem[];
    int* sX = smem;                        // 6*16*34 = 3264 ints
    int* sW = smem + 6 * 16 * 34;          // 64*144  = 9216 ints

    int tid = threadIdx.x;
    int b = blockIdx.x, h0 = blockIdx.y * 4, o0 = blockIdx.z * 64;
    int tw = tid & 31, og = tid >> 5;

    const int* gx = reinterpret_cast<const int*>(g_xq);
    const int* gw = reinterpret_cast<const int*>(g_wq);

    int acc[8][4];
#pragma unroll
    for (int i = 0; i < 8; ++i)
#pragma unroll
        for (int j = 0; j < 4; ++j) acc[i][j] = 0;

    for (int ch = 0; ch < 4; ++ch) {
        // Load X slice: padded rows h0..h0+5, channel words ch*16 .. ch*16+15
        for (int idx = tid; idx < 6 * 34 * 16; idx += 256) {
            int cw  = idx & 15;
            int rem = idx >> 4;
            int wp  = rem % 34;
            int r   = rem / 34;
            sX[(r * 16 + cw) * 34 + wp] =
                gx[((size_t)(b * 34 + h0 + r) * 34 + wp) * 64 + ch * 16 + cw];
        }
        // Load W slice: 64 o, 9 taps, 16 words (contiguous 576B per o)
        for (int idx = tid; idx < 64 * 144; idx += 256) {
            int o = idx / 144;
            int r = idx - o * 144;
            sW[idx] = gw[((size_t)((o0 + o) * 4 + ch)) * 144 + r];
        }
        __syncthreads();

        for (int t = 0; t < 9; ++t) {
            int ky = t / 3, kx = t % 3;
            const int* sXb = &sX[ky * 16 * 34 + tw + kx];
            const int* sWp = &sW[og * 8 * 144 + t * 16];
#pragma unroll 4
            for (int cw = 0; cw < 16; ++cw) {
                int x0 = sXb[(0 * 16 + cw) * 34];
                int x1 = sXb[(1 * 16 + cw) * 34];
                int x2 = sXb[(2 * 16 + cw) * 34];
                int x3 = sXb[(3 * 16 + cw) * 34];
#pragma unroll
                for (int i = 0; i < 8; ++i) {
                    int wv = sWp[i * 144 + cw];   // warp-broadcast
                    acc[i][0] = __dp4a(x0, wv, acc[i][0]);
                    acc[i][1] = __dp4a(x1, wv, acc[i][1]);
                    acc[i][2] = __dp4a(x2, wv, acc[i][2]);
                    acc[i][3] = __dp4a(x3, wv, acc[i][3]);
                }
            }
        }
        __syncthreads();
    }

    // Epilogue: y = (acc*2^-7)*inv + bias ; out = clip(rint(y*2), -2, 1) * 0.5
    // (ops kept un-fused / same order as reference for exact rounding match)
#pragma unroll
    for (int i = 0; i < 8; ++i) {
        int o = o0 + og * 8 + i;
        float sc = g_scale[o], bs = g_bias[o];
#pragma unroll
        for (int j = 0; j < 4; ++j) {
            float y = __fmul_rn(__fmul_rn((float)acc[i][j], 0.0078125f), sc);
            y = __fadd_rn(y, bs);
            float r = rintf(__fmul_rn(y, 2.0f));
            r = fminf(fmaxf(r, -2.0f), 1.0f);
            out[(((size_t)(b * 256 + o)) * 32 + h0 + j) * 32 + tw] = __fmul_rn(r, 0.5f);
        }
    }
}

extern "C" void kernel_launch(void* const* d_in, const int* in_sizes, int n_in,
                              void* d_out, int out_size) {
    const float* x     = (const float*)d_in[0];
    const float* wt    = (const float*)d_in[1];
    const float* gamma = (const float*)d_in[2];
    const float* beta  = (const float*)d_in[3];
    const float* mean  = (const float*)d_in[4];
    const float* var   = (const float*)d_in[5];
    float* out = (float*)d_out;

    // Zero padded input scratch (provides the conv halo)
    void* xq_ptr = nullptr;
    cudaGetSymbolAddress(&xq_ptr, g_xq);
    cudaMemsetAsync(xq_ptr, 0, sizeof(g_xq), 0);

    quantX_kernel<<<dim3(32, 32), 256>>>(x);
    quantW_kernel<<<2304, 256>>>(wt);
    bn_kernel<<<1, 256>>>(gamma, beta, mean, var);

    int smem_bytes = (6 * 16 * 34 + 64 * 144) * 4;   // 49920 B > 48KB -> opt in
    cudaFuncSetAttribute(conv_kernel, cudaFuncAttributeMaxDynamicSharedMemorySize, smem_bytes);
    conv_kernel<<<dim3(32, 8, 4), 256, smem_bytes>>>(out);
}